// round 4
// baseline (speedup 1.0000x reference)
#include <cuda_runtime.h>
#include <math.h>

#define NB   1024
#define NK   16
#define NG   2000
#define IND  4000
#define NH   256

#define BM1  32
#define BK1  16
#define BM4  16
#define BM5  8

// ---------------- scratch (static device globals; no dynamic alloc) ----------------
__device__ float g_logits[2*NB*NK];
__device__ float g_w[2*NB*NK];
__device__ float g_wsum[NB];
__device__ float g_agg[2*NB*IND];   // 32 MB: aggregated nf per graph
__device__ float g_pre[4*NB*NH];    // H1pre, H2pre, Dpre, Rpre
__device__ float g_proj[2*NB*NH];   // proj1, proj2

// ---------------- f32x2 helpers (Blackwell packed fp32) ----------------
__device__ __forceinline__ unsigned long long pack2(float x, float y){
    unsigned long long r;
    asm("mov.b64 %0, {%1, %2};" : "=l"(r) : "f"(x), "f"(y));
    return r;
}
__device__ __forceinline__ float2 unpack2(unsigned long long v){
    float2 f;
    asm("mov.b64 {%0, %1}, %2;" : "=f"(f.x), "=f"(f.y) : "l"(v));
    return f;
}
__device__ __forceinline__ unsigned long long fma2(unsigned long long a,
                                                   unsigned long long b,
                                                   unsigned long long c){
    unsigned long long d;
    asm("fma.rn.f32x2 %0, %1, %2, %3;" : "=l"(d) : "l"(a), "l"(b), "l"(c));
    return d;
}

// ---------------- K0: copy encoder_input into out[:, 0:4000] ----------------
__global__ void k_copy(const float* __restrict__ enc, float* __restrict__ out){
    int b = blockIdx.x;
    const float4* src = (const float4*)(enc + (size_t)b*IND);
    float4* dst = (float4*)(out + (size_t)b*(IND+NH));
    for (int j = threadIdx.x; j < IND/4; j += blockDim.x) dst[j] = src[j];
}

// ---------------- K1: fused gather+log + attention GEMM + tanh + Wa2 dot ----------------
// rows r in [0, 32768): graph g = r>>14, b = (r&16383)>>4, k = r&15
__global__ void __launch_bounds__(256, 2) k_attention(
    const float* __restrict__ sp, const float* __restrict__ un,
    const int* __restrict__ idx1, const int* __restrict__ idx2,
    const float* __restrict__ Wa1, const float* __restrict__ ba1,
    const float* __restrict__ Wa2, const float* __restrict__ ba2)
{
    __shared__ __align__(16) float As[BM1][BK1];
    __shared__ float Bs[BK1][NH];
    __shared__ int   cells[BM1];
    __shared__ float part[8][BM1];

    const int tid  = threadIdx.x;
    const int row0 = blockIdx.x * BM1;

    if (tid < BM1) {
        int r  = row0 + tid;
        int g  = r >> 14;
        int bk = r & 16383;
        cells[tid] = (g == 0) ? idx1[bk] : idx2[bk];
    }
    const float my_ba1 = ba1[tid];
    const float my_wa2 = Wa2[tid];
    __syncthreads();

    unsigned long long acc[BM1];
    #pragma unroll
    for (int m = 0; m < BM1; m++) acc[m] = 0ULL;

    const int m_ld = tid >> 3;          // 32 rows, 8 threads per row
    const int c_ld = (tid & 7) * 2;     // 2 consecutive cols each
    const int mycell = cells[m_ld];

    for (int k0 = 0; k0 < IND; k0 += BK1) {
        // A tile: gathered + log-transformed features (16-col chunk never straddles the 2000 boundary)
        {
            int d = k0 + c_ld;
            const float* srcp = (d < NG) ? (sp + (size_t)mycell*NG + d)
                                         : (un + (size_t)mycell*NG + (d - NG));
            float2 v = *(const float2*)srcp;
            As[m_ld][c_ld]   = __logf(0.01f + v.x);
            As[m_ld][c_ld+1] = __logf(0.01f + v.y);
        }
        // B tile
        #pragma unroll
        for (int i = 0; i < BK1; i++)
            Bs[i][tid] = __ldg(Wa1 + (size_t)(k0+i)*NH + tid);
        __syncthreads();

        unsigned long long bp[BK1/2];
        #pragma unroll
        for (int j = 0; j < BK1/2; j++)
            bp[j] = pack2(Bs[2*j][tid], Bs[2*j+1][tid]);

        #pragma unroll
        for (int m = 0; m < BM1; m++) {
            const unsigned long long* ap = (const unsigned long long*)(&As[m][0]);
            #pragma unroll
            for (int j = 0; j < BK1/2; j++)
                acc[m] = fma2(ap[j], bp[j], acc[m]);
        }
        __syncthreads();
    }

    // epilogue: tanh + dot with Wa2, reduce across 256 threads per row
    const int lane = tid & 31, warp = tid >> 5;
    #pragma unroll
    for (int m = 0; m < BM1; m++) {
        float2 a2 = unpack2(acc[m]);
        float v = tanhf(a2.x + a2.y + my_ba1) * my_wa2;
        #pragma unroll
        for (int off = 16; off > 0; off >>= 1)
            v += __shfl_xor_sync(0xffffffffu, v, off);
        if (lane == 0) part[warp][m] = v;
    }
    __syncthreads();
    if (tid < BM1) {
        float s = 0.f;
        #pragma unroll
        for (int w = 0; w < 8; w++) s += part[w][tid];
        g_logits[row0 + tid] = s + ba2[0];
    }
}

// ---------------- K2: softmax over K, weight multiply, normalize ----------------
__global__ void k_softmax(const float* __restrict__ nw1, const float* __restrict__ nw2){
    int idx = blockIdx.x * blockDim.x + threadIdx.x;
    if (idx >= 2*NB) return;
    int g = idx >> 10;
    int b = idx & (NB-1);
    const float* wr = g ? nw2 : nw1;
    int base = (g << 14) + (b << 4);
    float lg[NK], mx = -1e30f;
    #pragma unroll
    for (int k = 0; k < NK; k++){ lg[k] = g_logits[base + k]; mx = fmaxf(mx, lg[k]); }
    float se = 0.f;
    #pragma unroll
    for (int k = 0; k < NK; k++){ lg[k] = __expf(lg[k] - mx); se += lg[k]; }
    float inv_se = 1.f / se;
    float w[NK], S = 0.f;
    #pragma unroll
    for (int k = 0; k < NK; k++){ w[k] = wr[(b<<4)+k] * (lg[k] * inv_se); S += w[k]; }
    float inv = 1.f / (S + 1e-12f);
    #pragma unroll
    for (int k = 0; k < NK; k++) g_w[base + k] = w[k] * inv;
    if (g == 0) g_wsum[b] = S * inv;
}

// ---------------- K3: weighted aggregation agg[g][b][:] = sum_k w * nf ----------------
__device__ __forceinline__ void axpy_log4(float4& a, float wk, float4 x){
    a.x += wk*__logf(0.01f+x.x);
    a.y += wk*__logf(0.01f+x.y);
    a.z += wk*__logf(0.01f+x.z);
    a.w += wk*__logf(0.01f+x.w);
}

__global__ void __launch_bounds__(256) k_aggregate(
    const float* __restrict__ sp, const float* __restrict__ un,
    const int* __restrict__ idx1, const int* __restrict__ idx2)
{
    int bi = blockIdx.x;            // 0..2047
    int g  = bi >> 10, b = bi & (NB-1);
    __shared__ int   cs[NK];
    __shared__ float ws[NK];
    int tid = threadIdx.x;
    if (tid < NK){
        cs[tid] = (g ? idx2 : idx1)[(b<<4)+tid];
        ws[tid] = g_w[(g<<14)+(b<<4)+tid];
    }
    __syncthreads();

    int d0 = tid * 4;               // always < 2000
    int d1 = d0 + 1024;
    bool h1 = (d1 < NG);
    float4 s0 = {0,0,0,0}, u0 = {0,0,0,0}, s1 = {0,0,0,0}, u1 = {0,0,0,0};
    #pragma unroll 4
    for (int k = 0; k < NK; k++){
        const float* bs = sp + (size_t)cs[k]*NG;
        const float* bu = un + (size_t)cs[k]*NG;
        float wk = ws[k];
        axpy_log4(s0, wk, *(const float4*)(bs + d0));
        axpy_log4(u0, wk, *(const float4*)(bu + d0));
        if (h1){
            axpy_log4(s1, wk, *(const float4*)(bs + d1));
            axpy_log4(u1, wk, *(const float4*)(bu + d1));
        }
    }
    float* outrow = g_agg + (size_t)bi * IND;
    *(float4*)(outrow + d0)      = s0;
    *(float4*)(outrow + NG + d0) = u0;
    if (h1){
        *(float4*)(outrow + d1)      = s1;
        *(float4*)(outrow + NG + d1) = u1;
    }
}

// ---------------- K4: grouped GEMM [4096 x 4000] @ [4000 x 256] + bias ----------------
// group 0: agg1@W1+b1  | group 1: agg2@W1+b1 | group 2: (agg1-wsum*enc)@Wd+bd | group 3: enc@Wr+br
__global__ void __launch_bounds__(256, 2) k_proj_gemm(
    const float* __restrict__ enc,
    const float* __restrict__ W1, const float* __restrict__ b1,
    const float* __restrict__ Wd, const float* __restrict__ bd,
    const float* __restrict__ Wr, const float* __restrict__ br)
{
    __shared__ __align__(16) float As[BM4][BK1];
    __shared__ float Bs[BK1][NH];
    __shared__ float wsum_s[BM4];

    const int tid   = threadIdx.x;
    const int group = blockIdx.y;
    const int b0    = blockIdx.x * BM4;

    const float* Wp  = (group <= 1) ? W1 : (group == 2 ? Wd : Wr);
    const float* bip = (group <= 1) ? b1 : (group == 2 ? bd : br);

    if (tid < BM4) wsum_s[tid] = g_wsum[b0 + tid];
    __syncthreads();

    unsigned long long acc[BM4];
    #pragma unroll
    for (int m = 0; m < BM4; m++) acc[m] = 0ULL;

    const int m_ld = tid >> 4;
    const int c_ld = tid & 15;
    const int brow = b0 + m_ld;

    for (int k0 = 0; k0 < IND; k0 += BK1){
        {
            int d = k0 + c_ld;
            float a;
            if (group == 0)      a = g_agg[(size_t)brow*IND + d];
            else if (group == 1) a = g_agg[(size_t)(NB + brow)*IND + d];
            else if (group == 2) a = g_agg[(size_t)brow*IND + d]
                                   - wsum_s[m_ld]*enc[(size_t)brow*IND + d];
            else                 a = enc[(size_t)brow*IND + d];
            As[m_ld][c_ld] = a;
        }
        #pragma unroll
        for (int i = 0; i < BK1; i++)
            Bs[i][tid] = __ldg(Wp + (size_t)(k0+i)*NH + tid);
        __syncthreads();

        unsigned long long bp[BK1/2];
        #pragma unroll
        for (int j = 0; j < BK1/2; j++)
            bp[j] = pack2(Bs[2*j][tid], Bs[2*j+1][tid]);

        #pragma unroll
        for (int m = 0; m < BM4; m++){
            const unsigned long long* ap = (const unsigned long long*)(&As[m][0]);
            #pragma unroll
            for (int j = 0; j < BK1/2; j++)
                acc[m] = fma2(ap[j], bp[j], acc[m]);
        }
        __syncthreads();
    }

    float bias = bip[tid];
    #pragma unroll
    for (int m = 0; m < BM4; m++){
        float2 a2 = unpack2(acc[m]);
        g_pre[(size_t)(group*NB + b0 + m)*NH + tid] = a2.x + a2.y + bias;
    }
}

// ---------------- K5: proj = relu(relu(pre) @ W2 + b2), both graphs ----------------
__global__ void __launch_bounds__(256) k_mlp2(const float* __restrict__ W2,
                                              const float* __restrict__ b2){
    __shared__ float hs[BM5][NH];
    int tid = threadIdx.x;
    int r0  = blockIdx.x * BM5;   // rows 0..2047 == g_pre groups 0,1
    #pragma unroll
    for (int m = 0; m < BM5; m++)
        hs[m][tid] = fmaxf(g_pre[(size_t)(r0+m)*NH + tid], 0.f);
    __syncthreads();
    float acc[BM5] = {};
    for (int kk = 0; kk < NH; kk++){
        float bv = __ldg(W2 + (size_t)kk*NH + tid);
        #pragma unroll
        for (int m = 0; m < BM5; m++) acc[m] += hs[m][kk]*bv;
    }
    float bias = b2[tid];
    #pragma unroll
    for (int m = 0; m < BM5; m++)
        g_proj[(size_t)(r0+m)*NH + tid] = fmaxf(acc[m] + bias, 0.f);
}

// ---------------- K6: gate combine + diff/residual relu + LayerNorm + message gate ----------------
__global__ void k_epilogue(
    const float* __restrict__ cg_gate, const float* __restrict__ msg_gate,
    const float* __restrict__ gamma,   const float* __restrict__ beta,
    float* __restrict__ out)
{
    int b = blockIdx.x;
    int n = threadIdx.x;
    float p1 = g_proj[(size_t)b*NH + n];
    float p2 = g_proj[(size_t)(NB + b)*NH + n];
    float gg = 1.f / (1.f + __expf(-cg_gate[n]));
    float p  = gg*p1 + (1.f - gg)*p2;
    p += fmaxf(g_pre[(size_t)(2*NB + b)*NH + n], 0.f);   // relu(diff@Wd+bd)
    p += fmaxf(g_pre[(size_t)(3*NB + b)*NH + n], 0.f);   // relu(enc@Wr+br)

    __shared__ float r1[8], r2[8];
    float s = p, q = p*p;
    int lane = n & 31, warp = n >> 5;
    #pragma unroll
    for (int off = 16; off > 0; off >>= 1){
        s += __shfl_xor_sync(0xffffffffu, s, off);
        q += __shfl_xor_sync(0xffffffffu, q, off);
    }
    if (lane == 0){ r1[warp] = s; r2[warp] = q; }
    __syncthreads();
    float ts = 0.f, tq = 0.f;
    #pragma unroll
    for (int w = 0; w < 8; w++){ ts += r1[w]; tq += r2[w]; }
    float mu  = ts * (1.f/NH);
    float var = tq * (1.f/NH) - mu*mu;
    float y = (p - mu) * rsqrtf(var + 1e-5f) * gamma[n] + beta[n];
    y *= 1.f / (1.f + __expf(-msg_gate[n]));
    out[(size_t)b*(IND+NH) + IND + n] = y;
}

// ---------------- launch ----------------
extern "C" void kernel_launch(void* const* d_in, const int* in_sizes, int n_in,
                              void* d_out, int out_size)
{
    const float* enc  = (const float*)d_in[0];
    const int*   idx1 = (const int*)  d_in[1];
    const float* nw1  = (const float*)d_in[2];
    const int*   idx2 = (const int*)  d_in[3];
    const float* nw2  = (const float*)d_in[4];
    const float* sp   = (const float*)d_in[5];
    const float* un   = (const float*)d_in[6];
    const float* W1   = (const float*)d_in[7];
    const float* b1   = (const float*)d_in[8];
    const float* W2   = (const float*)d_in[9];
    const float* b2   = (const float*)d_in[10];
    const float* Wa1  = (const float*)d_in[11];
    const float* ba1  = (const float*)d_in[12];
    const float* Wa2  = (const float*)d_in[13];
    const float* ba2  = (const float*)d_in[14];
    const float* Wd   = (const float*)d_in[15];
    const float* bd   = (const float*)d_in[16];
    const float* Wr   = (const float*)d_in[17];
    const float* br   = (const float*)d_in[18];
    const float* gam  = (const float*)d_in[19];
    const float* bet  = (const float*)d_in[20];
    const float* mg   = (const float*)d_in[21];
    const float* cgg  = (const float*)d_in[22];
    float* out = (float*)d_out;

    k_copy     <<<NB, 256>>>(enc, out);
    k_attention<<<(2*NB*NK)/BM1, 256>>>(sp, un, idx1, idx2, Wa1, ba1, Wa2, ba2);
    k_softmax  <<<(2*NB + 255)/256, 256>>>(nw1, nw2);
    k_aggregate<<<2*NB, 256>>>(sp, un, idx1, idx2);
    dim3 g4(NB/BM4, 4);
    k_proj_gemm<<<g4, 256>>>(enc, W1, b1, Wd, bd, Wr, br);
    k_mlp2     <<<2*NB/BM5, 256>>>(W2, b2);
    k_epilogue <<<NB, 256>>>(cgg, mg, gam, bet, out);
}

// round 5
// speedup vs baseline: 2.6577x; 2.6577x over previous
#include <cuda_runtime.h>
#include <math.h>

#define NB   1024
#define NK   16
#define NG   2000
#define IND  4000
#define NH   256

// mma tiling
#define BM   64
#define BK   16
#define APAD 20      // conflict-free A-frag LDS: (20*row)%32 spans all offsets
#define BPAD 264     // conflict-free B-frag LDS: (8*k + n)%32 covers 32 banks
#define BM5  8

// ---------------- scratch (static device globals; no dynamic alloc) ----------------
__device__ float g_logits[2*NB*NK];
__device__ float g_w[2*NB*NK];
__device__ float g_wsum[NB];
__device__ float g_agg[2*NB*IND];      // 32 MB aggregated nf per graph
__device__ float g_pre[2][4*NB*NH];    // split-K partials: H1pre,H2pre,Dpre,Rpre
__device__ float g_proj[2*NB*NH];

// ---------------- tf32 mma ----------------
__device__ __forceinline__ void mma_tf32(float c[4], const unsigned a[4],
                                         unsigned b0, unsigned b1){
    asm volatile(
        "mma.sync.aligned.m16n8k8.row.col.f32.tf32.tf32.f32 "
        "{%0,%1,%2,%3}, {%4,%5,%6,%7}, {%8,%9}, {%0,%1,%2,%3};"
        : "+f"(c[0]), "+f"(c[1]), "+f"(c[2]), "+f"(c[3])
        : "r"(a[0]), "r"(a[1]), "r"(a[2]), "r"(a[3]), "r"(b0), "r"(b1));
}

// one BK=16 tile = two k8 steps. warp covers m32 x n64.
__device__ __forceinline__ void compute_tile(
    const float (*As)[APAD], const float (*Bs)[BPAD],
    int warp_m, int warp_n, int gid, int tig, float acc[2][8][4])
{
    #pragma unroll
    for (int s = 0; s < 2; s++){
        unsigned a[2][4];
        #pragma unroll
        for (int t = 0; t < 2; t++){
            int row = warp_m*32 + t*16 + gid;
            int col = s*8 + tig;
            a[t][0] = __float_as_uint(As[row][col]);
            a[t][1] = __float_as_uint(As[row+8][col]);
            a[t][2] = __float_as_uint(As[row][col+4]);
            a[t][3] = __float_as_uint(As[row+8][col+4]);
        }
        #pragma unroll
        for (int nf = 0; nf < 8; nf++){
            int n = warp_n*64 + nf*8 + gid;
            unsigned b0 = __float_as_uint(Bs[s*8+tig][n]);
            unsigned b1 = __float_as_uint(Bs[s*8+tig+4][n]);
            mma_tf32(acc[0][nf], a[0], b0, b1);
            mma_tf32(acc[1][nf], a[1], b0, b1);
        }
    }
}

// ---------------- K0: copy encoder_input into out[:, 0:4000] ----------------
__global__ void k_copy(const float* __restrict__ enc, float* __restrict__ out){
    int b = blockIdx.x;
    const float4* src = (const float4*)(enc + (size_t)b*IND);
    float4* dst = (float4*)(out + (size_t)b*(IND+NH));
    for (int j = threadIdx.x; j < IND/4; j += blockDim.x) dst[j] = src[j];
}

// ---------------- K1: fused gather+log A, tf32 mma GEMM, tanh+Wa2 epilogue ----------------
__global__ void __launch_bounds__(256, 2) k_attn_mma(
    const float* __restrict__ sp, const float* __restrict__ un,
    const int* __restrict__ idx1, const int* __restrict__ idx2,
    const float* __restrict__ Wa1, const float* __restrict__ ba1,
    const float* __restrict__ Wa2, const float* __restrict__ ba2)
{
    __shared__ __align__(16) float As[2][BM][APAD];
    __shared__ __align__(16) float Bs[2][BK][BPAD];
    __shared__ int   cells[BM];
    __shared__ float red[4][BM];

    const int tid  = threadIdx.x;
    const int row0 = blockIdx.x * BM;

    if (tid < BM){
        int gr = row0 + tid;
        cells[tid] = (gr < NB*NK) ? idx1[gr] : idx2[gr - NB*NK];
    }
    __syncthreads();

    const int wid = tid >> 5, lane = tid & 31;
    const int warp_m = wid & 1, warp_n = wid >> 1;
    const int gid = lane >> 2, tig = lane & 3;

    // A loader: thread -> (row, 4 cols)
    const int ar = tid >> 2;
    const int ac = (tid & 3) * 4;
    const int cell = cells[ar];
    const float* a_sp = sp + (size_t)cell*NG;
    const float* a_un = un + (size_t)cell*NG;
    // B loader: thread -> (k row, 16 cols)
    const int bk_r = tid >> 4;
    const int bn0  = (tid & 15) * 16;

    float acc[2][8][4];
    #pragma unroll
    for (int t=0;t<2;t++)
        #pragma unroll
        for (int nf=0;nf<8;nf++)
            #pragma unroll
            for (int c=0;c<4;c++) acc[t][nf][c] = 0.f;

    float4 aL; float4 bL[4];
    auto load_t = [&](int k0){
        int d = k0 + ac;                       // 4 | 2000 -> float4 never straddles
        const float* src = (d < NG) ? (a_sp + d) : (a_un + d - NG);
        float4 v = *(const float4*)src;
        aL.x = __logf(0.01f+v.x); aL.y = __logf(0.01f+v.y);
        aL.z = __logf(0.01f+v.z); aL.w = __logf(0.01f+v.w);
        const float* bp = Wa1 + (size_t)(k0 + bk_r)*NH + bn0;
        #pragma unroll
        for (int j=0;j<4;j++) bL[j] = *(const float4*)(bp + j*4);
    };
    auto store_t = [&](int buf){
        *(float4*)&As[buf][ar][ac] = aL;
        #pragma unroll
        for (int j=0;j<4;j++) *(float4*)&Bs[buf][bk_r][bn0 + j*4] = bL[j];
    };

    load_t(0); store_t(0); __syncthreads();
    const int NT = IND / BK;                   // 250
    for (int t = 0; t < NT; t++){
        int cur = t & 1;
        if (t+1 < NT) load_t((t+1)*BK);
        compute_tile(As[cur], Bs[cur], warp_m, warp_n, gid, tig, acc);
        if (t+1 < NT){ store_t(cur ^ 1); __syncthreads(); }
    }

    // epilogue: logit_row = sum_n tanh(pre + ba1[n]) * Wa2[n]
    float s0[2] = {0.f,0.f}, s1[2] = {0.f,0.f};
    #pragma unroll
    for (int nf=0; nf<8; nf++){
        int n0 = warp_n*64 + nf*8 + tig*2;
        float ba_0 = __ldg(ba1+n0), ba_1 = __ldg(ba1+n0+1);
        float w_0  = __ldg(Wa2+n0), w_1  = __ldg(Wa2+n0+1);
        #pragma unroll
        for (int t=0;t<2;t++){
            s0[t] += tanhf(acc[t][nf][0]+ba_0)*w_0 + tanhf(acc[t][nf][1]+ba_1)*w_1;
            s1[t] += tanhf(acc[t][nf][2]+ba_0)*w_0 + tanhf(acc[t][nf][3]+ba_1)*w_1;
        }
    }
    #pragma unroll
    for (int off=1; off<=2; off<<=1){
        #pragma unroll
        for (int t=0;t<2;t++){
            s0[t] += __shfl_xor_sync(0xffffffffu, s0[t], off);
            s1[t] += __shfl_xor_sync(0xffffffffu, s1[t], off);
        }
    }
    if (tig == 0){
        #pragma unroll
        for (int t=0;t<2;t++){
            int r = warp_m*32 + t*16 + gid;
            red[warp_n][r]   = s0[t];
            red[warp_n][r+8] = s1[t];
        }
    }
    __syncthreads();
    if (tid < BM){
        float v = red[0][tid]+red[1][tid]+red[2][tid]+red[3][tid] + __ldg(ba2);
        g_logits[row0 + tid] = v;
    }
}

// ---------------- K2: softmax over K, weight multiply, normalize ----------------
__global__ void k_softmax(const float* __restrict__ nw1, const float* __restrict__ nw2){
    int idx = blockIdx.x * blockDim.x + threadIdx.x;
    if (idx >= 2*NB) return;
    int g = idx >> 10;
    int b = idx & (NB-1);
    const float* wr = g ? nw2 : nw1;
    int base = (g << 14) + (b << 4);
    float lg[NK], mx = -1e30f;
    #pragma unroll
    for (int k = 0; k < NK; k++){ lg[k] = g_logits[base + k]; mx = fmaxf(mx, lg[k]); }
    float se = 0.f;
    #pragma unroll
    for (int k = 0; k < NK; k++){ lg[k] = __expf(lg[k] - mx); se += lg[k]; }
    float inv_se = 1.f / se;
    float w[NK], S = 0.f;
    #pragma unroll
    for (int k = 0; k < NK; k++){ w[k] = wr[(b<<4)+k] * (lg[k] * inv_se); S += w[k]; }
    float inv = 1.f / (S + 1e-12f);
    #pragma unroll
    for (int k = 0; k < NK; k++) g_w[base + k] = w[k] * inv;
    if (g == 0) g_wsum[b] = S * inv;
}

// ---------------- K3: weighted aggregation ----------------
__device__ __forceinline__ void axpy_log4(float4& a, float wk, float4 x){
    a.x += wk*__logf(0.01f+x.x);
    a.y += wk*__logf(0.01f+x.y);
    a.z += wk*__logf(0.01f+x.z);
    a.w += wk*__logf(0.01f+x.w);
}

__global__ void __launch_bounds__(256) k_aggregate(
    const float* __restrict__ sp, const float* __restrict__ un,
    const int* __restrict__ idx1, const int* __restrict__ idx2)
{
    int bi = blockIdx.x;            // 0..2047
    int g  = bi >> 10, b = bi & (NB-1);
    __shared__ int   cs[NK];
    __shared__ float ws[NK];
    int tid = threadIdx.x;
    if (tid < NK){
        cs[tid] = (g ? idx2 : idx1)[(b<<4)+tid];
        ws[tid] = g_w[(g<<14)+(b<<4)+tid];
    }
    __syncthreads();

    int d0 = tid * 4;
    int d1 = d0 + 1024;
    bool h1 = (d1 < NG);
    float4 s0 = {0,0,0,0}, u0 = {0,0,0,0}, s1 = {0,0,0,0}, u1 = {0,0,0,0};
    #pragma unroll 4
    for (int k = 0; k < NK; k++){
        const float* bs = sp + (size_t)cs[k]*NG;
        const float* bu = un + (size_t)cs[k]*NG;
        float wk = ws[k];
        axpy_log4(s0, wk, *(const float4*)(bs + d0));
        axpy_log4(u0, wk, *(const float4*)(bu + d0));
        if (h1){
            axpy_log4(s1, wk, *(const float4*)(bs + d1));
            axpy_log4(u1, wk, *(const float4*)(bu + d1));
        }
    }
    float* outrow = g_agg + (size_t)bi * IND;
    *(float4*)(outrow + d0)      = s0;
    *(float4*)(outrow + NG + d0) = u0;
    if (h1){
        *(float4*)(outrow + d1)      = s1;
        *(float4*)(outrow + NG + d1) = u1;
    }
}

// ---------------- K4: grouped tf32 mma GEMM, split-K=2 ----------------
// group 0: agg1@W1 | 1: agg2@W1 | 2: (agg1-wsum*enc)@Wd | 3: enc@Wr
__global__ void __launch_bounds__(256, 2) k_proj_mma(
    const float* __restrict__ enc,
    const float* __restrict__ W1, const float* __restrict__ b1,
    const float* __restrict__ Wd, const float* __restrict__ bd,
    const float* __restrict__ Wr, const float* __restrict__ br)
{
    __shared__ __align__(16) float As[2][BM][APAD];
    __shared__ __align__(16) float Bs[2][BK][BPAD];
    __shared__ float wsum_s[BM];

    const int tid   = threadIdx.x;
    const int group = blockIdx.y;
    const int kz    = blockIdx.z;
    const int rb0   = blockIdx.x * BM;

    const float* Wp  = (group <= 1) ? W1 : (group == 2 ? Wd : Wr);
    const float* bip = (group <= 1) ? b1 : (group == 2 ? bd : br);

    if (tid < BM) wsum_s[tid] = g_wsum[rb0 + tid];
    __syncthreads();

    const int wid = tid >> 5, lane = tid & 31;
    const int warp_m = wid & 1, warp_n = wid >> 1;
    const int gid = lane >> 2, tig = lane & 3;

    const int ar = tid >> 2;
    const int ac = (tid & 3) * 4;
    const int rb = rb0 + ar;
    const float wsum = wsum_s[ar];
    const float* aggp = g_agg + ((group==1) ? (size_t)(NB+rb)*IND : (size_t)rb*IND);
    const float* encp = enc + (size_t)rb*IND;
    const int bk_r = tid >> 4;
    const int bn0  = (tid & 15) * 16;

    float acc[2][8][4];
    #pragma unroll
    for (int t=0;t<2;t++)
        #pragma unroll
        for (int nf=0;nf<8;nf++)
            #pragma unroll
            for (int c=0;c<4;c++) acc[t][nf][c] = 0.f;

    const int kbase = kz * (IND/2);
    float4 aL; float4 bL[4];
    auto load_t = [&](int k0){
        int d = kbase + k0 + ac;
        float4 v;
        if (group == 3) v = *(const float4*)(encp + d);
        else {
            v = *(const float4*)(aggp + d);
            if (group == 2){
                float4 e = *(const float4*)(encp + d);
                v.x -= wsum*e.x; v.y -= wsum*e.y; v.z -= wsum*e.z; v.w -= wsum*e.w;
            }
        }
        aL = v;
        const float* bp = Wp + (size_t)(kbase + k0 + bk_r)*NH + bn0;
        #pragma unroll
        for (int j=0;j<4;j++) bL[j] = *(const float4*)(bp + j*4);
    };
    auto store_t = [&](int buf){
        *(float4*)&As[buf][ar][ac] = aL;
        #pragma unroll
        for (int j=0;j<4;j++) *(float4*)&Bs[buf][bk_r][bn0 + j*4] = bL[j];
    };

    load_t(0); store_t(0); __syncthreads();
    const int NT = (IND/2) / BK;               // 125
    for (int t = 0; t < NT; t++){
        int cur = t & 1;
        if (t+1 < NT) load_t((t+1)*BK);
        compute_tile(As[cur], Bs[cur], warp_m, warp_n, gid, tig, acc);
        if (t+1 < NT){ store_t(cur ^ 1); __syncthreads(); }
    }

    const int grow0 = group*NB + rb0;
    float* outp = g_pre[kz];
    #pragma unroll
    for (int nf=0; nf<8; nf++){
        int n0 = warp_n*64 + nf*8 + tig*2;
        float bb0 = (kz==0) ? __ldg(bip+n0)   : 0.f;
        float bb1 = (kz==0) ? __ldg(bip+n0+1) : 0.f;
        #pragma unroll
        for (int t=0;t<2;t++){
            int r = grow0 + warp_m*32 + t*16 + gid;
            outp[(size_t)r*NH + n0]         = acc[t][nf][0] + bb0;
            outp[(size_t)r*NH + n0 + 1]     = acc[t][nf][1] + bb1;
            outp[(size_t)(r+8)*NH + n0]     = acc[t][nf][2] + bb0;
            outp[(size_t)(r+8)*NH + n0 + 1] = acc[t][nf][3] + bb1;
        }
    }
}

// ---------------- K5: proj = relu(relu(pre) @ W2 + b2), both graphs ----------------
__global__ void __launch_bounds__(256) k_mlp2(const float* __restrict__ W2,
                                              const float* __restrict__ b2){
    __shared__ float hs[BM5][NH];
    int tid = threadIdx.x;
    int r0  = blockIdx.x * BM5;   // rows 0..2047 (groups 0,1)
    #pragma unroll
    for (int m = 0; m < BM5; m++){
        size_t i = (size_t)(r0+m)*NH + tid;
        hs[m][tid] = fmaxf(g_pre[0][i] + g_pre[1][i], 0.f);
    }
    __syncthreads();
    float acc[BM5] = {};
    for (int kk = 0; kk < NH; kk++){
        float bv = __ldg(W2 + (size_t)kk*NH + tid);
        #pragma unroll
        for (int m = 0; m < BM5; m++) acc[m] += hs[m][kk]*bv;
    }
    float bias = b2[tid];
    #pragma unroll
    for (int m = 0; m < BM5; m++)
        g_proj[(size_t)(r0+m)*NH + tid] = fmaxf(acc[m] + bias, 0.f);
}

// ---------------- K6: gate combine + diff/residual relu + LayerNorm + gate ----------------
__global__ void k_epilogue(
    const float* __restrict__ cg_gate, const float* __restrict__ msg_gate,
    const float* __restrict__ gamma,   const float* __restrict__ beta,
    float* __restrict__ out)
{
    int b = blockIdx.x;
    int n = threadIdx.x;
    float p1 = g_proj[(size_t)b*NH + n];
    float p2 = g_proj[(size_t)(NB + b)*NH + n];
    float gg = 1.f / (1.f + __expf(-cg_gate[n]));
    float p  = gg*p1 + (1.f - gg)*p2;
    size_t id = (size_t)(2*NB + b)*NH + n;
    size_t ir = (size_t)(3*NB + b)*NH + n;
    p += fmaxf(g_pre[0][id] + g_pre[1][id], 0.f);   // relu(diff@Wd+bd)
    p += fmaxf(g_pre[0][ir] + g_pre[1][ir], 0.f);   // relu(enc@Wr+br)

    __shared__ float r1[8], r2[8];
    float s = p, q = p*p;
    int lane = n & 31, warp = n >> 5;
    #pragma unroll
    for (int off = 16; off > 0; off >>= 1){
        s += __shfl_xor_sync(0xffffffffu, s, off);
        q += __shfl_xor_sync(0xffffffffu, q, off);
    }
    if (lane == 0){ r1[warp] = s; r2[warp] = q; }
    __syncthreads();
    float ts = 0.f, tq = 0.f;
    #pragma unroll
    for (int w = 0; w < 8; w++){ ts += r1[w]; tq += r2[w]; }
    float mu  = ts * (1.f/NH);
    float var = tq * (1.f/NH) - mu*mu;
    float y = (p - mu) * rsqrtf(var + 1e-5f) * gamma[n] + beta[n];
    y *= 1.f / (1.f + __expf(-msg_gate[n]));
    out[(size_t)b*(IND+NH) + IND + n] = y;
}

// ---------------- launch ----------------
extern "C" void kernel_launch(void* const* d_in, const int* in_sizes, int n_in,
                              void* d_out, int out_size)
{
    const float* enc  = (const float*)d_in[0];
    const int*   idx1 = (const int*)  d_in[1];
    const float* nw1  = (const float*)d_in[2];
    const int*   idx2 = (const int*)  d_in[3];
    const float* nw2  = (const float*)d_in[4];
    const float* sp   = (const float*)d_in[5];
    const float* un   = (const float*)d_in[6];
    const float* W1   = (const float*)d_in[7];
    const float* b1   = (const float*)d_in[8];
    const float* W2   = (const float*)d_in[9];
    const float* b2   = (const float*)d_in[10];
    const float* Wa1  = (const float*)d_in[11];
    const float* ba1  = (const float*)d_in[12];
    const float* Wa2  = (const float*)d_in[13];
    const float* ba2  = (const float*)d_in[14];
    const float* Wd   = (const float*)d_in[15];
    const float* bd   = (const float*)d_in[16];
    const float* Wr   = (const float*)d_in[17];
    const float* br   = (const float*)d_in[18];
    const float* gam  = (const float*)d_in[19];
    const float* bet  = (const float*)d_in[20];
    const float* mg   = (const float*)d_in[21];
    const float* cgg  = (const float*)d_in[22];
    float* out = (float*)d_out;

    k_copy     <<<NB, 256>>>(enc, out);
    k_attn_mma <<<(2*NB*NK)/BM, 256>>>(sp, un, idx1, idx2, Wa1, ba1, Wa2, ba2);
    k_softmax  <<<(2*NB + 255)/256, 256>>>(nw1, nw2);
    k_aggregate<<<2*NB, 256>>>(sp, un, idx1, idx2);
    dim3 gp(NB/BM, 4, 2);
    k_proj_mma <<<gp, 256>>>(enc, W1, b1, Wd, bd, Wr, br);
    k_mlp2     <<<2*NB/BM5, 256>>>(W2, b2);
    k_epilogue <<<NB, 256>>>(cgg, mg, gam, bet, out);
}